// round 13
// baseline (speedup 1.0000x reference)
#include <cuda_runtime.h>
#include <cuda_fp16.h>
#include <math.h>
#include <stdint.h>

#define HH   256
#define HW   65536
#define WHF  129
#define DIM  128
#define HID  512
#define NB   4
#define NLAYERS 4
#define FSTRIDE 272   // padded row stride (float2) for the FFT shared buffer

typedef __half f16;

// ---------------- scratch (device globals) ----------------
__device__ float  g_h[(size_t)NB * DIM * HW];          // residual [b][c][p] fp32
__device__ float  g_z[(size_t)NB * DIM * HW];          // fft input fp32
__device__ __align__(16) float2 g_xf[(size_t)NB * DIM * WHF * 256];
__device__ __align__(16) float2 g_filt[(size_t)DIM * WHF * 256];
__device__ f16    g_h16[(size_t)NB * DIM * HW];        // fp16 activations
__device__ f16    g_y16[(size_t)NB * HID * HW];
__device__ f16    g_z16[(size_t)NB * DIM * HW];
__device__ f16    g_w1h[(size_t)NLAYERS * HID * DIM], g_w1l[(size_t)NLAYERS * HID * DIM];
__device__ f16    g_w2h[(size_t)NLAYERS * DIM * HID], g_w2l[(size_t)NLAYERS * DIM * HID];
__device__ f16    g_oxh[(size_t)NLAYERS * DIM * DIM], g_oxl[(size_t)NLAYERS * DIM * DIM];

// ---------------- helpers ----------------
__device__ __forceinline__ float2 cadd(float2 a, float2 b){ return make_float2(a.x+b.x, a.y+b.y); }
__device__ __forceinline__ float2 csub(float2 a, float2 b){ return make_float2(a.x-b.x, a.y-b.y); }
__device__ __forceinline__ float2 cmul(float2 a, float2 b){
    return make_float2(a.x*b.x - a.y*b.y, a.x*b.y + a.y*b.x);
}
__device__ __forceinline__ float2 cmulc(float2 a, float2 b){   // a * conj(b)
    return make_float2(a.x*b.x + a.y*b.y, a.y*b.x - a.x*b.y);
}
__device__ __forceinline__ uint32_t smem_u32(const void* p) {
    uint32_t a;
    asm("{ .reg .u64 t; cvta.to.shared.u64 t, %1; cvt.u32.u64 %0, t; }" : "=r"(a) : "l"(p));
    return a;
}
__device__ __forceinline__ uint32_t pack_f16x2(float a, float b) {
    return ((uint32_t)__half_as_ushort(__float2half_rn(b)) << 16)
         |  (uint32_t)__half_as_ushort(__float2half_rn(a));
}

// ================= mma.sync primitives =================
__device__ __forceinline__ void ldsm4(uint32_t* r, uint32_t addr) {
    asm volatile("ldmatrix.sync.aligned.m8n8.x4.shared.b16 {%0,%1,%2,%3}, [%4];"
                 : "=r"(r[0]), "=r"(r[1]), "=r"(r[2]), "=r"(r[3]) : "r"(addr));
}
__device__ __forceinline__ void ldsm4t(uint32_t* r, uint32_t addr) {
    asm volatile("ldmatrix.sync.aligned.m8n8.x4.trans.shared.b16 {%0,%1,%2,%3}, [%4];"
                 : "=r"(r[0]), "=r"(r[1]), "=r"(r[2]), "=r"(r[3]) : "r"(addr));
}
__device__ __forceinline__ void mma16816(float* c, const uint32_t* a, const uint32_t* b) {
    asm volatile(
        "mma.sync.aligned.m16n8k16.row.col.f32.f16.f16.f32 "
        "{%0,%1,%2,%3}, {%4,%5,%6,%7}, {%8,%9}, {%0,%1,%2,%3};"
        : "+f"(c[0]), "+f"(c[1]), "+f"(c[2]), "+f"(c[3])
        : "r"(a[0]), "r"(a[1]), "r"(a[2]), "r"(a[3]), "r"(b[0]), "r"(b[1]));
}
__device__ __forceinline__ void cp16(uint32_t dst, const void* src) {
    asm volatile("cp.async.cg.shared.global [%0], [%1], 16;" :: "r"(dst), "l"(src));
}

// ================= fp16 2-pass pipelined tensor-core GEMM, 64-wide k-chunks =================
// 512 threads, tile 128m x 256n, warp grid 4x4. A = weights fp16 hi/lo, B = act fp16.
// Stage layout (64KB): [Ah 16K][Al 16K][B 32K], 3 stages.
// EPI: 0 -> fp32 Cf; 1 -> silu -> f16 Ch; 2 -> +res(Cf) -> Cf + f16 Ch
template <int K, int M, int EPI>
__global__ void __launch_bounds__(512, 1)
gemm_mma(const f16* __restrict__ Ah, const f16* __restrict__ Al,
         const f16* __restrict__ Bm,
         const float* __restrict__ bias,
         float* __restrict__ Cf, f16* __restrict__ Ch)
{
    constexpr int NC = K / 64;
    constexpr int STAGE = 65536;
    extern __shared__ uint8_t smem[];
    uint32_t sbase = smem_u32(smem);

    int tid  = threadIdx.x;
    int lane = tid & 31;
    int warp = tid >> 5;
    int wm = warp >> 2, wn = warp & 3;

    const f16* Ahp = Ah + (size_t)blockIdx.y * 128 * K;
    const f16* Alp = Al + (size_t)blockIdx.y * 128 * K;
    const f16* Bp  = Bm + (size_t)blockIdx.z * K * HW + blockIdx.x * 256;

    // per-thread copy slots: A 2 lines/split, B 4 lines
    const f16* gA[2][2];        // [split][it]
    uint32_t   oA[2][2];
    const f16* gB[4];
    uint32_t   oB[4];
#pragma unroll
    for (int it = 0; it < 2; it++) {
        int L = tid + it * 512;             // 0..1023
        int tile = L >> 5, line = L & 31;   // tile = m16*4 + kb
        int m16 = tile >> 2, kb = tile & 3;
        int m = m16 * 16 + (line & 15);
        int kofs = kb * 16 + (line >> 4) * 8;
        size_t aoff = (size_t)m * K + kofs;
        gA[0][it] = Ahp + aoff;  oA[0][it] = tile * 512 + line * 16;
        gA[1][it] = Alp + aoff;  oA[1][it] = oA[0][it] + 16384;
    }
#pragma unroll
    for (int it = 0; it < 4; it++) {
        int L = tid + it * 512;             // 0..2047
        int kb = L >> 9, g = L & 511;
        int n16 = g >> 5, line = g & 31;
        int k = kb * 16 + (line & 15);
        int n8 = n16 * 2 + (line >> 4);
        gB[it] = Bp + (size_t)k * HW + n8 * 8;
        oB[it] = 32768 + (kb * 16 + n16) * 512 + line * 16;
    }

    auto issue = [&](int c) {
        uint32_t sst = sbase + (c % 3) * STAGE;
#pragma unroll
        for (int it = 0; it < 2; it++) {
            cp16(sst + oA[0][it], gA[0][it]);  gA[0][it] += 64;
            cp16(sst + oA[1][it], gA[1][it]);  gA[1][it] += 64;
        }
#pragma unroll
        for (int it = 0; it < 4; it++) {
            cp16(sst + oB[it], gB[it]);  gB[it] += (size_t)64 * HW;
        }
        asm volatile("cp.async.commit_group;" ::: "memory");
    };

    float acc[2][8][4] = {};

    issue(0);
    if (NC > 1) issue(1);

    for (int c = 0; c < NC; c++) {
        if (c + 1 < NC) {
            asm volatile("cp.async.wait_group 1;" ::: "memory");
        } else {
            asm volatile("cp.async.wait_group 0;" ::: "memory");
        }
        __syncthreads();
        uint32_t st = sbase + (c % 3) * STAGE;
#pragma unroll
        for (int kb = 0; kb < 4; kb++) {
            uint32_t ah[2][4], al[2][4];
#pragma unroll
            for (int i = 0; i < 2; i++) {
                uint32_t ad = st + (((wm * 2 + i) * 4 + kb) << 9) + lane * 16;
                ldsm4(ah[i], ad);
                ldsm4(al[i], ad + 16384);
            }
#pragma unroll
            for (int r = 0; r < 4; r++) {
                uint32_t bh[4];
                uint32_t bd = st + 32768 + ((kb * 16 + wn * 4 + r) << 9) + lane * 16;
                ldsm4t(bh, bd);
#pragma unroll
                for (int i = 0; i < 2; i++)
#pragma unroll
                    for (int hh = 0; hh < 2; hh++) {
                        float* a_ = acc[i][r * 2 + hh];
                        mma16816(a_, ah[i], &bh[hh * 2]);
                        mma16816(a_, al[i], &bh[hh * 2]);
                    }
            }
        }
        __syncthreads();
        if (c + 2 < NC) issue(c + 2);
    }

    int g = lane >> 2;
    int mb0   = blockIdx.y * 128 + wm * 32;
    int nbase = blockIdx.x * 256 + wn * 64 + (lane & 3) * 2;
    size_t batch = (size_t)blockIdx.z * M * HW;
#pragma unroll
    for (int i = 0; i < 2; i++) {
        int r0 = mb0 + i * 16 + g;
        float bi0 = bias[r0], bi1 = bias[r0 + 8];
        size_t o0 = batch + (size_t)r0 * HW + nbase;
        size_t o1 = o0 + (size_t)8 * HW;
#pragma unroll
        for (int j = 0; j < 8; j++) {
            float v0 = acc[i][j][0] + bi0, v1 = acc[i][j][1] + bi0;
            float v2 = acc[i][j][2] + bi1, v3 = acc[i][j][3] + bi1;
            if (EPI == 1) {
                v0 = v0 / (1.f + __expf(-v0)); v1 = v1 / (1.f + __expf(-v1));
                v2 = v2 / (1.f + __expf(-v2)); v3 = v3 / (1.f + __expf(-v3));
            }
            if (EPI == 2) {
                float2 r0f = *(float2*)(Cf + o0 + j * 8);
                float2 r1f = *(float2*)(Cf + o1 + j * 8);
                v0 += r0f.x; v1 += r0f.y; v2 += r1f.x; v3 += r1f.y;
            }
            if (EPI == 0 || EPI == 2) {
                *(float2*)(Cf + o0 + j * 8) = make_float2(v0, v1);
                *(float2*)(Cf + o1 + j * 8) = make_float2(v2, v3);
            }
            if (EPI == 1 || EPI == 2) {
                *(uint32_t*)(Ch + o0 + j * 8) = pack_f16x2(v0, v1);
                *(uint32_t*)(Ch + o1 + j * 8) = pack_f16x2(v2, v3);
            }
        }
    }
}

// ---------------- weight split (fp16 hi/lo) ----------------
__global__ void wsplit(const float* __restrict__ w, f16* __restrict__ wh,
                       f16* __restrict__ wl, int n)
{
    int i = blockIdx.x * 256 + threadIdx.x;
    if (i >= n) return;
    float v = w[i];
    f16 h = __float2half_rn(v);
    wh[i] = h;
    wl[i] = __float2half_rn(v - __half2float(h));
}

// ================= four-step register FFT (256 = 16 x 16), R12 verified =================
__device__ __forceinline__ float2 tw16mul(float2 v, float c, float s, bool inv) {
    float ss = inv ? -s : s;
    return make_float2(v.x * c - v.y * ss, v.x * ss + v.y * c);
}

template <bool INV>
__device__ __forceinline__ void dft16(float2* x) {
    float2 u[16];
#pragma unroll
    for (int j1 = 0; j1 < 4; j1++) {
        float2 a = x[j1], b = x[j1 + 4], c = x[j1 + 8], d = x[j1 + 12];
        float2 t0 = cadd(a, c), t1 = csub(a, c);
        float2 t2 = cadd(b, d), t3 = csub(b, d);
        float2 r3 = INV ? make_float2(-t3.y, t3.x) : make_float2(t3.y, -t3.x);
        u[j1 * 4 + 0] = cadd(t0, t2);
        u[j1 * 4 + 1] = cadd(t1, r3);
        u[j1 * 4 + 2] = csub(t0, t2);
        u[j1 * 4 + 3] = csub(t1, r3);
    }
    u[5]  = tw16mul(u[5],  0.92387953f, -0.38268343f, INV);
    u[6]  = tw16mul(u[6],  0.70710678f, -0.70710678f, INV);
    u[7]  = tw16mul(u[7],  0.38268343f, -0.92387953f, INV);
    u[9]  = tw16mul(u[9],  0.70710678f, -0.70710678f, INV);
    u[10] = tw16mul(u[10], 0.0f,        -1.0f,        INV);
    u[11] = tw16mul(u[11], -0.70710678f,-0.70710678f, INV);
    u[13] = tw16mul(u[13], 0.38268343f, -0.92387953f, INV);
    u[14] = tw16mul(u[14], -0.70710678f,-0.70710678f, INV);
    u[15] = tw16mul(u[15], -0.92387953f, 0.38268343f, INV);
#pragma unroll
    for (int a = 0; a < 4; a++) {
        float2 p = u[a], q = u[4 + a], r = u[8 + a], s = u[12 + a];
        float2 t0 = cadd(p, r), t1 = csub(p, r);
        float2 t2 = cadd(q, s), t3 = csub(q, s);
        float2 r3 = INV ? make_float2(-t3.y, t3.x) : make_float2(t3.y, -t3.x);
        x[a + 0]  = cadd(t0, t2);
        x[a + 4]  = cadd(t1, r3);
        x[a + 8]  = csub(t0, t2);
        x[a + 12] = csub(t1, r3);
    }
}

#define TW256_INIT()                                                     \
    do { float s_, c_;                                                   \
        sincospif(-(float)threadIdx.x / 128.0f, &s_, &c_);               \
        tw[threadIdx.x] = make_float2(c_, s_); } while (0)

__global__ void fft_row_fwd(const float* __restrict__ z, float2* __restrict__ xf)
{
    __shared__ float2 sb[16 * FSTRIDE];
    __shared__ float2 tw[256];
    TW256_INIT();
    int tid = threadIdx.x;
    int r = tid >> 4, q1 = tid & 15;
    int img = blockIdx.x, y0 = blockIdx.y * 16;
    const float* src = z + (size_t)img * HW + (size_t)y0 * 256;
    for (int q = tid; q < 1024; q += 256) {
        float4 v = ((const float4*)src)[q];
        float2* rp = &sb[(q >> 6) * FSTRIDE + (q & 63) * 4];
        rp[0] = make_float2(v.x, 0.f); rp[1] = make_float2(v.y, 0.f);
        rp[2] = make_float2(v.z, 0.f); rp[3] = make_float2(v.w, 0.f);
    }
    __syncthreads();
    float2 X[16];
#pragma unroll
    for (int n2 = 0; n2 < 16; n2++) X[n2] = sb[r * FSTRIDE + q1 + 16 * n2];
    __syncthreads();
    dft16<false>(X);
#pragma unroll
    for (int k1 = 0; k1 < 16; k1++) X[k1] = cmul(X[k1], tw[q1 * k1]);
#pragma unroll
    for (int k1 = 0; k1 < 16; k1++) sb[r * FSTRIDE + k1 * 17 + q1] = X[k1];
    __syncthreads();
#pragma unroll
    for (int j = 0; j < 16; j++) X[j] = sb[r * FSTRIDE + q1 * 17 + j];
    dft16<false>(X);
    __syncthreads();
#pragma unroll
    for (int k2 = 0; k2 < 16; k2++) sb[r * FSTRIDE + q1 + 16 * k2] = X[k2];
    __syncthreads();
    float2* dst = xf + (size_t)img * (WHF * 256) + y0;
    for (int idx = tid; idx < WHF * 16; idx += 256) {
        int kx = idx >> 4, ry = idx & 15;
        dst[(size_t)kx * 256 + ry] = sb[ry * FSTRIDE + kx];
    }
}

__global__ void fft_col(float2* __restrict__ xf, const float2* __restrict__ filt)
{
    __shared__ float2 sb[16 * FSTRIDE];
    __shared__ float2 tw[256];
    TW256_INIT();
    int tid = threadIdx.x;
    int r = tid >> 4, q1 = tid & 15;
    size_t l0 = (size_t)blockIdx.x * 16;
    float2* src = xf + l0 * 256;
    const float4* src4 = (const float4*)src;
    for (int q = tid; q < 2048; q += 256)
        ((float4*)&sb[(q >> 7) * FSTRIDE])[q & 127] = src4[q];
    __syncthreads();
    float2 X[16];
#pragma unroll
    for (int n2 = 0; n2 < 16; n2++) X[n2] = sb[r * FSTRIDE + q1 + 16 * n2];
    __syncthreads();
    dft16<false>(X);
#pragma unroll
    for (int k1 = 0; k1 < 16; k1++) X[k1] = cmul(X[k1], tw[q1 * k1]);
#pragma unroll
    for (int k1 = 0; k1 < 16; k1++) sb[r * FSTRIDE + k1 * 17 + q1] = X[k1];
    __syncthreads();
#pragma unroll
    for (int j = 0; j < 16; j++) X[j] = sb[r * FSTRIDE + q1 * 17 + j];
    dft16<false>(X);
    {
        size_t fl = ((l0 + r) % (size_t)(DIM * WHF)) * 256;
#pragma unroll
        for (int k2 = 0; k2 < 16; k2++)
            X[k2] = cmul(X[k2], filt[fl + q1 + 16 * k2]);
    }
    dft16<true>(X);
#pragma unroll
    for (int n1 = 0; n1 < 16; n1++) X[n1] = cmulc(X[n1], tw[q1 * n1]);
    __syncthreads();
#pragma unroll
    for (int n1 = 0; n1 < 16; n1++) sb[r * FSTRIDE + n1 * 17 + q1] = X[n1];
    __syncthreads();
#pragma unroll
    for (int j = 0; j < 16; j++) X[j] = sb[r * FSTRIDE + q1 * 17 + j];
    dft16<true>(X);
    __syncthreads();
#pragma unroll
    for (int n2 = 0; n2 < 16; n2++) sb[r * FSTRIDE + q1 + 16 * n2] = X[n2];
    __syncthreads();
    float4* dst4 = (float4*)src;
    for (int q = tid; q < 2048; q += 256)
        dst4[q] = ((float4*)&sb[(q >> 7) * FSTRIDE])[q & 127];
}

__global__ void fft_row_inv(const float2* __restrict__ xf, f16* __restrict__ zh)
{
    __shared__ float2 sb[16 * FSTRIDE];
    __shared__ float2 tw[256];
    TW256_INIT();
    int tid = threadIdx.x;
    int r = tid >> 4, q1 = tid & 15;
    int img = blockIdx.x, y0 = blockIdx.y * 16;
    const float2* src = xf + (size_t)img * (WHF * 256) + y0;
    for (int idx = tid; idx < WHF * 16; idx += 256) {
        int kx = idx >> 4, ry = idx & 15;
        sb[ry * FSTRIDE + kx] = src[(size_t)kx * 256 + ry];
    }
    __syncthreads();
    for (int q = tid; q < 16 * 127; q += 256) {
        int rr = q / 127;
        int k = 129 + (q % 127);
        float2 v = sb[rr * FSTRIDE + 256 - k];
        sb[rr * FSTRIDE + k] = make_float2(v.x, -v.y);
    }
    __syncthreads();
    float2 X[16];
#pragma unroll
    for (int k2 = 0; k2 < 16; k2++) X[k2] = sb[r * FSTRIDE + q1 + 16 * k2];
    __syncthreads();
    dft16<true>(X);
#pragma unroll
    for (int n1 = 0; n1 < 16; n1++) X[n1] = cmulc(X[n1], tw[q1 * n1]);
#pragma unroll
    for (int n1 = 0; n1 < 16; n1++) sb[r * FSTRIDE + n1 * 17 + q1] = X[n1];
    __syncthreads();
#pragma unroll
    for (int j = 0; j < 16; j++) X[j] = sb[r * FSTRIDE + q1 * 17 + j];
    dft16<true>(X);
    __syncthreads();
#pragma unroll
    for (int n2 = 0; n2 < 16; n2++) sb[r * FSTRIDE + q1 + 16 * n2] = X[n2];
    __syncthreads();
    size_t o = (size_t)img * HW + (size_t)y0 * 256;
    for (int idx = tid; idx < 2048; idx += 256) {
        float v0 = sb[(idx >> 7) * FSTRIDE + (idx & 127) * 2].x;
        float v1 = sb[(idx >> 7) * FSTRIDE + (idx & 127) * 2 + 1].x;
        *(uint32_t*)(zh + o + idx * 2) = pack_f16x2(v0, v1);
    }
}

// ---------------- enc / dec / filter ----------------
__global__ void enc_kernel(const float* __restrict__ x, const float* __restrict__ w,
                           const float* __restrict__ bias, const float* __restrict__ pos,
                           float* __restrict__ h, f16* __restrict__ hh)
{
    int idx = blockIdx.x * 256 + threadIdx.x;
    if (idx >= NB * DIM * HW / 2) return;
    int e = idx * 2;
    int p = e & (HW - 1);
    int o = (e >> 16) & (DIM - 1);
    int b = e >> 23;
    float x0 = x[(size_t)(b * 2 + 0) * HW + p];
    float x1 = x[(size_t)(b * 2 + 1) * HW + p];
    float x0b = x[(size_t)(b * 2 + 0) * HW + p + 1];
    float x1b = x[(size_t)(b * 2 + 1) * HW + p + 1];
    float w0 = w[o * 2], w1 = w[o * 2 + 1], bb = bias[o];
    float v0 = (w0 * x0 + w1 * x1 + bb) * 8.0f + pos[(size_t)o * HW + p];
    float v1 = (w0 * x0b + w1 * x1b + bb) * 8.0f + pos[(size_t)o * HW + p + 1];
    *(float2*)(h + e) = make_float2(v0, v1);
    *(uint32_t*)(hh + e) = pack_f16x2(v0, v1);
}

__global__ void dec_kernel(const float* __restrict__ h, const float* __restrict__ w,
                           const float* __restrict__ bias, float* __restrict__ out)
{
    int idx = blockIdx.x * 256 + threadIdx.x;
    if (idx >= NB * HW) return;
    int p = idx & (HW - 1);
    int b = idx >> 16;
    const float* hb = h + (size_t)b * DIM * HW + p;
    float a0 = 0.f, a1 = 0.f;
#pragma unroll 4
    for (int c = 0; c < DIM; c++) {
        float hv = hb[(size_t)c * HW];
        a0 += w[c] * hv;
        a1 += w[DIM + c] * hv;
    }
    out[(size_t)(b * 2 + 0) * HW + p] = (a0 + bias[0]) * 0.125f;
    out[(size_t)(b * 2 + 1) * HW + p] = (a1 + bias[1]) * 0.125f;
}

__global__ void prep_filt(const float* __restrict__ mags, const float* __restrict__ phases,
                          float2* __restrict__ filt)
{
    int idx = blockIdx.x * 256 + threadIdx.x;
    if (idx >= DIM * HH * WHF) return;
    int kx = idx % WHF;
    int ky = (idx / WHF) % HH;
    int c  = idx / (WHF * HH);
    int kyp = (ky <= 128) ? ky : (256 - ky);
    float2 o = make_float2(0.f, 0.f);
    if (kx * kx + kyp * kyp <= 16384) {
        float sig = 1.0f / (1.0f + __expf(-mags[idx]));
        float s, co;
        sincosf(phases[idx], &s, &co);
        float sc = sig * (1.0f / 65536.0f);
        o = make_float2(sc * co, sc * s);
    }
    filt[(size_t)c * (WHF * 256) + (size_t)kx * 256 + ky] = o;   // natural ky
}

// ---------------- launch ----------------
extern "C" void kernel_launch(void* const* d_in, const int* in_sizes, int n_in,
                              void* d_out, int out_size)
{
    const float* x      = (const float*)d_in[0];
    const float* enc_w  = (const float*)d_in[1];
    const float* enc_b  = (const float*)d_in[2];
    const float* pos    = (const float*)d_in[3];
    const float* w1     = (const float*)d_in[4];
    const float* b1     = (const float*)d_in[5];
    const float* w2     = (const float*)d_in[6];
    const float* b2     = (const float*)d_in[7];
    const float* mags   = (const float*)d_in[8];
    const float* phases = (const float*)d_in[9];
    const float* oxw    = (const float*)d_in[10];
    const float* oxb    = (const float*)d_in[11];
    const float* dw     = (const float*)d_in[12];
    const float* db     = (const float*)d_in[13];
    float* out = (float*)d_out;

    float *h, *z;
    float2 *xf, *ft;
    f16 *hh, *yh, *zh, *w1h, *w1l, *w2h, *w2l, *oxh, *oxl;
    cudaGetSymbolAddress((void**)&h,   g_h);
    cudaGetSymbolAddress((void**)&z,   g_z);
    cudaGetSymbolAddress((void**)&xf,  g_xf);
    cudaGetSymbolAddress((void**)&ft,  g_filt);
    cudaGetSymbolAddress((void**)&hh,  g_h16);
    cudaGetSymbolAddress((void**)&yh,  g_y16);
    cudaGetSymbolAddress((void**)&zh,  g_z16);
    cudaGetSymbolAddress((void**)&w1h, g_w1h);
    cudaGetSymbolAddress((void**)&w1l, g_w1l);
    cudaGetSymbolAddress((void**)&w2h, g_w2h);
    cudaGetSymbolAddress((void**)&w2l, g_w2l);
    cudaGetSymbolAddress((void**)&oxh, g_oxh);
    cudaGetSymbolAddress((void**)&oxl, g_oxl);

    const int SMEM = 3 * 65536;                      // 192 KB
    static bool attr = false;
    if (!attr) {
        cudaFuncSetAttribute(gemm_mma<128, 512, 1>, cudaFuncAttributeMaxDynamicSharedMemorySize, SMEM);
        cudaFuncSetAttribute(gemm_mma<512, 128, 0>, cudaFuncAttributeMaxDynamicSharedMemorySize, SMEM);
        cudaFuncSetAttribute(gemm_mma<128, 128, 2>, cudaFuncAttributeMaxDynamicSharedMemorySize, SMEM);
        attr = true;
    }

    wsplit<<<(NLAYERS * HID * DIM + 255) / 256, 256>>>(w1, w1h, w1l, NLAYERS * HID * DIM);
    wsplit<<<(NLAYERS * DIM * HID + 255) / 256, 256>>>(w2, w2h, w2l, NLAYERS * DIM * HID);
    wsplit<<<(NLAYERS * DIM * DIM + 255) / 256, 256>>>(oxw, oxh, oxl, NLAYERS * DIM * DIM);

    enc_kernel<<<(NB * DIM * HW / 2 + 255) / 256, 256>>>(x, enc_w, enc_b, pos, h, hh);

    const size_t specL = (size_t)DIM * HH * WHF;
    for (int i = 0; i < NLAYERS; i++) {
        prep_filt<<<(int)((specL + 255) / 256), 256>>>(mags + i * specL, phases + i * specL, ft);

        gemm_mma<128, 512, 1><<<dim3(256, 4, NB), 512, SMEM>>>(
            w1h + (size_t)i * HID * DIM, w1l + (size_t)i * HID * DIM,
            hh, b1 + i * HID, nullptr, yh);
        gemm_mma<512, 128, 0><<<dim3(256, 1, NB), 512, SMEM>>>(
            w2h + (size_t)i * DIM * HID, w2l + (size_t)i * DIM * HID,
            yh, b2 + i * DIM, z, nullptr);

        fft_row_fwd<<<dim3(NB * DIM, 16), 256>>>(z, xf);
        fft_col<<<(NB * DIM * WHF) / 16, 256>>>(xf, ft);
        fft_row_inv<<<dim3(NB * DIM, 16), 256>>>(xf, zh);

        gemm_mma<128, 128, 2><<<dim3(256, 1, NB), 512, SMEM>>>(
            oxh + (size_t)i * DIM * DIM, oxl + (size_t)i * DIM * DIM,
            zh, oxb + i * DIM, h, hh);
    }

    dec_kernel<<<(NB * HW + 255) / 256, 256>>>(h, dw, db, out);
}

// round 14
// speedup vs baseline: 1.0956x; 1.0956x over previous
#include <cuda_runtime.h>
#include <cuda_fp16.h>
#include <math.h>
#include <stdint.h>

#define HH   256
#define HW   65536
#define WHF  129
#define DIM  128
#define HID  512
#define NB   4
#define NLAYERS 4
#define FSTRIDE 272   // padded row stride (float2) for the FFT shared buffer

typedef __half f16;

// ---------------- scratch (device globals) ----------------
__device__ float  g_h[(size_t)NB * DIM * HW];          // residual [b][c][p] fp32
__device__ float  g_z[(size_t)NB * DIM * HW];          // fft input fp32
__device__ __align__(16) float2 g_xf[(size_t)NB * DIM * WHF * 256];
__device__ __align__(16) float2 g_filt[(size_t)DIM * WHF * 256];
__device__ f16    g_h16[(size_t)NB * DIM * HW];        // fp16 activations
__device__ f16    g_y16[(size_t)NB * HID * HW];
__device__ f16    g_z16[(size_t)NB * DIM * HW];
__device__ f16    g_w1h[(size_t)NLAYERS * HID * DIM], g_w1l[(size_t)NLAYERS * HID * DIM];
__device__ f16    g_w2h[(size_t)NLAYERS * DIM * HID], g_w2l[(size_t)NLAYERS * DIM * HID];
__device__ f16    g_oxh[(size_t)NLAYERS * DIM * DIM], g_oxl[(size_t)NLAYERS * DIM * DIM];

// ---------------- helpers ----------------
__device__ __forceinline__ float2 cadd(float2 a, float2 b){ return make_float2(a.x+b.x, a.y+b.y); }
__device__ __forceinline__ float2 csub(float2 a, float2 b){ return make_float2(a.x-b.x, a.y-b.y); }
__device__ __forceinline__ float2 cmul(float2 a, float2 b){
    return make_float2(a.x*b.x - a.y*b.y, a.x*b.y + a.y*b.x);
}
__device__ __forceinline__ float2 cmulc(float2 a, float2 b){   // a * conj(b)
    return make_float2(a.x*b.x + a.y*b.y, a.y*b.x - a.x*b.y);
}
__device__ __forceinline__ uint32_t smem_u32(const void* p) {
    uint32_t a;
    asm("{ .reg .u64 t; cvta.to.shared.u64 t, %1; cvt.u32.u64 %0, t; }" : "=r"(a) : "l"(p));
    return a;
}
__device__ __forceinline__ uint32_t pack_f16x2(float a, float b) {
    return ((uint32_t)__half_as_ushort(__float2half_rn(b)) << 16)
         |  (uint32_t)__half_as_ushort(__float2half_rn(a));
}

// ================= mma.sync primitives =================
__device__ __forceinline__ void ldsm4(uint32_t* r, uint32_t addr) {
    asm volatile("ldmatrix.sync.aligned.m8n8.x4.shared.b16 {%0,%1,%2,%3}, [%4];"
                 : "=r"(r[0]), "=r"(r[1]), "=r"(r[2]), "=r"(r[3]) : "r"(addr));
}
__device__ __forceinline__ void ldsm4t(uint32_t* r, uint32_t addr) {
    asm volatile("ldmatrix.sync.aligned.m8n8.x4.trans.shared.b16 {%0,%1,%2,%3}, [%4];"
                 : "=r"(r[0]), "=r"(r[1]), "=r"(r[2]), "=r"(r[3]) : "r"(addr));
}
__device__ __forceinline__ void mma16816(float* c, const uint32_t* a, const uint32_t* b) {
    asm volatile(
        "mma.sync.aligned.m16n8k16.row.col.f32.f16.f16.f32 "
        "{%0,%1,%2,%3}, {%4,%5,%6,%7}, {%8,%9}, {%0,%1,%2,%3};"
        : "+f"(c[0]), "+f"(c[1]), "+f"(c[2]), "+f"(c[3])
        : "r"(a[0]), "r"(a[1]), "r"(a[2]), "r"(a[3]), "r"(b[0]), "r"(b[1]));
}
__device__ __forceinline__ void cp16(uint32_t dst, const void* src) {
    asm volatile("cp.async.cg.shared.global [%0], [%1], 16;" :: "r"(dst), "l"(src));
}

// ================= fp16 2-pass pipelined tensor-core GEMM (R12, verified) =================
template <int K, int M, int EPI>
__global__ void __launch_bounds__(512, 1)
gemm_mma(const f16* __restrict__ Ah, const f16* __restrict__ Al,
         const f16* __restrict__ Bm,
         const float* __restrict__ bias,
         float* __restrict__ Cf, f16* __restrict__ Ch)
{
    constexpr int NC = K / 32;
    constexpr int STAGE = 32768;
    extern __shared__ uint8_t smem[];
    uint32_t sbase = smem_u32(smem);

    int tid  = threadIdx.x;
    int lane = tid & 31;
    int warp = tid >> 5;
    int wm = warp >> 2, wn = warp & 3;

    const f16* Ahp = Ah + (size_t)blockIdx.y * 128 * K;
    const f16* Alp = Al + (size_t)blockIdx.y * 128 * K;
    const f16* Bp  = Bm + (size_t)blockIdx.z * K * HW + blockIdx.x * 256;

    const f16* gp[4];
    uint32_t   off[4];
    {
        int tile = tid >> 5, line = tid & 31;
        int am  = ((tile >> 1) << 4) + (line & 15);
        int agg = ((tile & 1) << 1) + (line >> 4);
        size_t aoff = (size_t)am * K + agg * 8;
        gp[0] = Ahp + aoff;  gp[1] = Alp + aoff;
        off[0] = tile * 512 + line * 16;
        off[1] = off[0] + 8192;
        int bk  = line & 15;
        int bgn = (tile & 15) * 2 + (line >> 4);
        gp[2] = Bp + (size_t)bk * HW + bgn * 8;
        gp[3] = Bp + (size_t)(bk + 16) * HW + bgn * 8;
        off[2] = 16384 + tile * 512 + line * 16;
        off[3] = 16384 + (tile + 16) * 512 + line * 16;
    }

    auto issue = [&](int c) {
        uint32_t sst = sbase + (c % 3) * STAGE;
        cp16(sst + off[0], gp[0]);  gp[0] += 32;
        cp16(sst + off[1], gp[1]);  gp[1] += 32;
        cp16(sst + off[2], gp[2]);  gp[2] += (size_t)32 * HW;
        cp16(sst + off[3], gp[3]);  gp[3] += (size_t)32 * HW;
        asm volatile("cp.async.commit_group;" ::: "memory");
    };

    float acc[2][8][4] = {};

    issue(0);
    if (NC > 1) issue(1);

    for (int c = 0; c < NC; c++) {
        if (c + 1 < NC) {
            asm volatile("cp.async.wait_group 1;" ::: "memory");
        } else {
            asm volatile("cp.async.wait_group 0;" ::: "memory");
        }
        __syncthreads();
        uint32_t st = sbase + (c % 3) * STAGE;
#pragma unroll
        for (int kb = 0; kb < 2; kb++) {
            uint32_t ah[2][4], al[2][4];
#pragma unroll
            for (int i = 0; i < 2; i++) {
                uint32_t ad = st + ((((wm * 2 + i) * 2) + kb) << 9) + lane * 16;
                ldsm4(ah[i], ad);
                ldsm4(al[i], ad + 8192);
            }
#pragma unroll
            for (int r = 0; r < 4; r++) {
                uint32_t bh[4];
                uint32_t bd = st + 16384 + ((kb * 16 + wn * 4 + r) << 9) + lane * 16;
                ldsm4t(bh, bd);
#pragma unroll
                for (int i = 0; i < 2; i++)
#pragma unroll
                    for (int hh = 0; hh < 2; hh++) {
                        float* a_ = acc[i][r * 2 + hh];
                        mma16816(a_, ah[i], &bh[hh * 2]);
                        mma16816(a_, al[i], &bh[hh * 2]);
                    }
            }
        }
        __syncthreads();
        if (c + 2 < NC) issue(c + 2);
    }

    int g = lane >> 2;
    int mb0   = blockIdx.y * 128 + wm * 32;
    int nbase = blockIdx.x * 256 + wn * 64 + (lane & 3) * 2;
    size_t batch = (size_t)blockIdx.z * M * HW;
#pragma unroll
    for (int i = 0; i < 2; i++) {
        int r0 = mb0 + i * 16 + g;
        float bi0 = bias[r0], bi1 = bias[r0 + 8];
        size_t o0 = batch + (size_t)r0 * HW + nbase;
        size_t o1 = o0 + (size_t)8 * HW;
#pragma unroll
        for (int j = 0; j < 8; j++) {
            float v0 = acc[i][j][0] + bi0, v1 = acc[i][j][1] + bi0;
            float v2 = acc[i][j][2] + bi1, v3 = acc[i][j][3] + bi1;
            if (EPI == 1) {
                v0 = v0 / (1.f + __expf(-v0)); v1 = v1 / (1.f + __expf(-v1));
                v2 = v2 / (1.f + __expf(-v2)); v3 = v3 / (1.f + __expf(-v3));
            }
            if (EPI == 2) {
                float2 r0f = *(float2*)(Cf + o0 + j * 8);
                float2 r1f = *(float2*)(Cf + o1 + j * 8);
                v0 += r0f.x; v1 += r0f.y; v2 += r1f.x; v3 += r1f.y;
            }
            if (EPI == 0 || EPI == 2) {
                *(float2*)(Cf + o0 + j * 8) = make_float2(v0, v1);
                *(float2*)(Cf + o1 + j * 8) = make_float2(v2, v3);
            }
            if (EPI == 1 || EPI == 2) {
                *(uint32_t*)(Ch + o0 + j * 8) = pack_f16x2(v0, v1);
                *(uint32_t*)(Ch + o1 + j * 8) = pack_f16x2(v2, v3);
            }
        }
    }
}

// ---------------- weight split (fp16 hi/lo) ----------------
__global__ void wsplit(const float* __restrict__ w, f16* __restrict__ wh,
                       f16* __restrict__ wl, int n)
{
    int i = blockIdx.x * 256 + threadIdx.x;
    if (i >= n) return;
    float v = w[i];
    f16 h = __float2half_rn(v);
    wh[i] = h;
    wl[i] = __float2half_rn(v - __half2float(h));
}

// ================= four-step register FFT (256 = 16 x 16) =================
__device__ __forceinline__ float2 tw16mul(float2 v, float c, float s, bool inv) {
    float ss = inv ? -s : s;
    return make_float2(v.x * c - v.y * ss, v.x * ss + v.y * c);
}

template <bool INV>
__device__ __forceinline__ void dft16(float2* x) {
    float2 u[16];
#pragma unroll
    for (int j1 = 0; j1 < 4; j1++) {
        float2 a = x[j1], b = x[j1 + 4], c = x[j1 + 8], d = x[j1 + 12];
        float2 t0 = cadd(a, c), t1 = csub(a, c);
        float2 t2 = cadd(b, d), t3 = csub(b, d);
        float2 r3 = INV ? make_float2(-t3.y, t3.x) : make_float2(t3.y, -t3.x);
        u[j1 * 4 + 0] = cadd(t0, t2);
        u[j1 * 4 + 1] = cadd(t1, r3);
        u[j1 * 4 + 2] = csub(t0, t2);
        u[j1 * 4 + 3] = csub(t1, r3);
    }
    u[5]  = tw16mul(u[5],  0.92387953f, -0.38268343f, INV);
    u[6]  = tw16mul(u[6],  0.70710678f, -0.70710678f, INV);
    u[7]  = tw16mul(u[7],  0.38268343f, -0.92387953f, INV);
    u[9]  = tw16mul(u[9],  0.70710678f, -0.70710678f, INV);
    u[10] = tw16mul(u[10], 0.0f,        -1.0f,        INV);
    u[11] = tw16mul(u[11], -0.70710678f,-0.70710678f, INV);
    u[13] = tw16mul(u[13], 0.38268343f, -0.92387953f, INV);
    u[14] = tw16mul(u[14], -0.70710678f,-0.70710678f, INV);
    u[15] = tw16mul(u[15], -0.92387953f, 0.38268343f, INV);
#pragma unroll
    for (int a = 0; a < 4; a++) {
        float2 p = u[a], q = u[4 + a], r = u[8 + a], s = u[12 + a];
        float2 t0 = cadd(p, r), t1 = csub(p, r);
        float2 t2 = cadd(q, s), t3 = csub(q, s);
        float2 r3 = INV ? make_float2(-t3.y, t3.x) : make_float2(t3.y, -t3.x);
        x[a + 0]  = cadd(t0, t2);
        x[a + 4]  = cadd(t1, r3);
        x[a + 8]  = csub(t0, t2);
        x[a + 12] = csub(t1, r3);
    }
}

#define TW256_INIT()                                                     \
    do { float s_, c_;                                                   \
        sincospif(-(float)threadIdx.x / 128.0f, &s_, &c_);               \
        tw[threadIdx.x] = make_float2(c_, s_); } while (0)

// x-row forward real FFT: direct-register input, smem-staged transposed output
__global__ void fft_row_fwd(const float* __restrict__ z, float2* __restrict__ xf)
{
    __shared__ float2 sb[16 * FSTRIDE];
    __shared__ float2 tw[256];
    TW256_INIT();
    int tid = threadIdx.x;
    int r = tid >> 4, q1 = tid & 15;
    int img = blockIdx.x, y0 = blockIdx.y * 16;
    const float* src = z + (size_t)img * HW + (size_t)(y0 + r) * 256;
    float2 X[16];
#pragma unroll
    for (int n2 = 0; n2 < 16; n2++) X[n2] = make_float2(src[q1 + 16 * n2], 0.f);
    __syncthreads();           // tw table ready
    dft16<false>(X);
#pragma unroll
    for (int k1 = 0; k1 < 16; k1++) X[k1] = cmul(X[k1], tw[q1 * k1]);
#pragma unroll
    for (int k1 = 0; k1 < 16; k1++) sb[r * FSTRIDE + k1 * 17 + q1] = X[k1];
    __syncthreads();
#pragma unroll
    for (int j = 0; j < 16; j++) X[j] = sb[r * FSTRIDE + q1 * 17 + j];
    dft16<false>(X);
    __syncthreads();
#pragma unroll
    for (int k2 = 0; k2 < 16; k2++) sb[r * FSTRIDE + q1 + 16 * k2] = X[k2];
    __syncthreads();
    float2* dst = xf + (size_t)img * (WHF * 256) + y0;
    for (int idx = tid; idx < WHF * 16; idx += 256) {
        int kx = idx >> 4, ry = idx & 15;
        dst[(size_t)kx * 256 + ry] = sb[ry * FSTRIDE + kx];
    }
}

// y-column: direct-register global load/store, fwd -> filter -> inv, 3 syncs
__global__ void fft_col(float2* __restrict__ xf, const float2* __restrict__ filt)
{
    __shared__ float2 sb[16 * FSTRIDE];
    __shared__ float2 tw[256];
    TW256_INIT();
    int tid = threadIdx.x;
    int r = tid >> 4, q1 = tid & 15;
    size_t l0 = (size_t)blockIdx.x * 16;
    float2* line = xf + (l0 + r) * 256;
    float2 X[16];
#pragma unroll
    for (int n2 = 0; n2 < 16; n2++) X[n2] = line[q1 + 16 * n2];   // coalesced 128B/16 lanes
    __syncthreads();           // tw ready
    dft16<false>(X);
#pragma unroll
    for (int k1 = 0; k1 < 16; k1++) X[k1] = cmul(X[k1], tw[q1 * k1]);
#pragma unroll
    for (int k1 = 0; k1 < 16; k1++) sb[r * FSTRIDE + k1 * 17 + q1] = X[k1];
    __syncthreads();
#pragma unroll
    for (int j = 0; j < 16; j++) X[j] = sb[r * FSTRIDE + q1 * 17 + j];
    dft16<false>(X);                                        // spec at ky = q1 + 16k2
    {
        size_t fl = ((l0 + r) % (size_t)(DIM * WHF)) * 256;
#pragma unroll
        for (int k2 = 0; k2 < 16; k2++)
            X[k2] = cmul(X[k2], filt[fl + q1 + 16 * k2]);
    }
    dft16<true>(X);
#pragma unroll
    for (int n1 = 0; n1 < 16; n1++) X[n1] = cmulc(X[n1], tw[q1 * n1]);
    __syncthreads();           // WAR on sb
#pragma unroll
    for (int n1 = 0; n1 < 16; n1++) sb[r * FSTRIDE + n1 * 17 + q1] = X[n1];
    __syncthreads();
#pragma unroll
    for (int j = 0; j < 16; j++) X[j] = sb[r * FSTRIDE + q1 * 17 + j];
    dft16<true>(X);                                         // x at n = q1 + 16n2
#pragma unroll
    for (int n2 = 0; n2 < 16; n2++) line[q1 + 16 * n2] = X[n2];   // coalesced
}

// x-row inverse (c2r): smem-staged transposed input, direct fp16 output
__global__ void fft_row_inv(const float2* __restrict__ xf, f16* __restrict__ zh)
{
    __shared__ float2 sb[16 * FSTRIDE];
    __shared__ float2 tw[256];
    TW256_INIT();
    int tid = threadIdx.x;
    int r = tid >> 4, q1 = tid & 15;
    int img = blockIdx.x, y0 = blockIdx.y * 16;
    const float2* src = xf + (size_t)img * (WHF * 256) + y0;
    for (int idx = tid; idx < WHF * 16; idx += 256) {
        int kx = idx >> 4, ry = idx & 15;
        sb[ry * FSTRIDE + kx] = src[(size_t)kx * 256 + ry];
    }
    __syncthreads();
    for (int q = tid; q < 16 * 127; q += 256) {             // Hermitian fill
        int rr = q / 127;
        int k = 129 + (q % 127);
        float2 v = sb[rr * FSTRIDE + 256 - k];
        sb[rr * FSTRIDE + k] = make_float2(v.x, -v.y);
    }
    __syncthreads();
    float2 X[16];
#pragma unroll
    for (int k2 = 0; k2 < 16; k2++) X[k2] = sb[r * FSTRIDE + q1 + 16 * k2];
    __syncthreads();
    dft16<true>(X);
#pragma unroll
    for (int n1 = 0; n1 < 16; n1++) X[n1] = cmulc(X[n1], tw[q1 * n1]);
#pragma unroll
    for (int n1 = 0; n1 < 16; n1++) sb[r * FSTRIDE + n1 * 17 + q1] = X[n1];
    __syncthreads();
#pragma unroll
    for (int j = 0; j < 16; j++) X[j] = sb[r * FSTRIDE + q1 * 17 + j];
    dft16<true>(X);                                         // x at n = q1 + 16n2
    // direct fp16 store: lane q1 holds n = q1+16n2; pack pairs via smem would cost a pass,
    // instead store 4B per element pairlessly: use u16 stores (2B) — keep smem path for packing.
    __syncthreads();
#pragma unroll
    for (int n2 = 0; n2 < 16; n2++) sb[r * FSTRIDE + q1 + 16 * n2] = X[n2];
    __syncthreads();
    size_t o = (size_t)img * HW + (size_t)(y0) * 256;
    for (int idx = tid; idx < 2048; idx += 256) {
        float v0 = sb[(idx >> 7) * FSTRIDE + (idx & 127) * 2].x;
        float v1 = sb[(idx >> 7) * FSTRIDE + (idx & 127) * 2 + 1].x;
        *(uint32_t*)(zh + o + idx * 2) = pack_f16x2(v0, v1);
    }
}

// ---------------- enc / dec / filter ----------------
__global__ void enc_kernel(const float* __restrict__ x, const float* __restrict__ w,
                           const float* __restrict__ bias, const float* __restrict__ pos,
                           float* __restrict__ h, f16* __restrict__ hh)
{
    int idx = blockIdx.x * 256 + threadIdx.x;
    if (idx >= NB * DIM * HW / 2) return;
    int e = idx * 2;
    int p = e & (HW - 1);
    int o = (e >> 16) & (DIM - 1);
    int b = e >> 23;
    float x0 = x[(size_t)(b * 2 + 0) * HW + p];
    float x1 = x[(size_t)(b * 2 + 1) * HW + p];
    float x0b = x[(size_t)(b * 2 + 0) * HW + p + 1];
    float x1b = x[(size_t)(b * 2 + 1) * HW + p + 1];
    float w0 = w[o * 2], w1 = w[o * 2 + 1], bb = bias[o];
    float v0 = (w0 * x0 + w1 * x1 + bb) * 8.0f + pos[(size_t)o * HW + p];
    float v1 = (w0 * x0b + w1 * x1b + bb) * 8.0f + pos[(size_t)o * HW + p + 1];
    *(float2*)(h + e) = make_float2(v0, v1);
    *(uint32_t*)(hh + e) = pack_f16x2(v0, v1);
}

__global__ void dec_kernel(const float* __restrict__ h, const float* __restrict__ w,
                           const float* __restrict__ bias, float* __restrict__ out)
{
    int idx = blockIdx.x * 256 + threadIdx.x;
    if (idx >= NB * HW) return;
    int p = idx & (HW - 1);
    int b = idx >> 16;
    const float* hb = h + (size_t)b * DIM * HW + p;
    float a0 = 0.f, a1 = 0.f;
#pragma unroll 4
    for (int c = 0; c < DIM; c++) {
        float hv = hb[(size_t)c * HW];
        a0 += w[c] * hv;
        a1 += w[DIM + c] * hv;
    }
    out[(size_t)(b * 2 + 0) * HW + p] = (a0 + bias[0]) * 0.125f;
    out[(size_t)(b * 2 + 1) * HW + p] = (a1 + bias[1]) * 0.125f;
}

__global__ void prep_filt(const float* __restrict__ mags, const float* __restrict__ phases,
                          float2* __restrict__ filt)
{
    int idx = blockIdx.x * 256 + threadIdx.x;
    if (idx >= DIM * HH * WHF) return;
    int kx = idx % WHF;
    int ky = (idx / WHF) % HH;
    int c  = idx / (WHF * HH);
    int kyp = (ky <= 128) ? ky : (256 - ky);
    float2 o = make_float2(0.f, 0.f);
    if (kx * kx + kyp * kyp <= 16384) {
        float sig = 1.0f / (1.0f + __expf(-mags[idx]));
        float s, co;
        sincosf(phases[idx], &s, &co);
        float sc = sig * (1.0f / 65536.0f);
        o = make_float2(sc * co, sc * s);
    }
    filt[(size_t)c * (WHF * 256) + (size_t)kx * 256 + ky] = o;   // natural ky
}

// ---------------- launch ----------------
extern "C" void kernel_launch(void* const* d_in, const int* in_sizes, int n_in,
                              void* d_out, int out_size)
{
    const float* x      = (const float*)d_in[0];
    const float* enc_w  = (const float*)d_in[1];
    const float* enc_b  = (const float*)d_in[2];
    const float* pos    = (const float*)d_in[3];
    const float* w1     = (const float*)d_in[4];
    const float* b1     = (const float*)d_in[5];
    const float* w2     = (const float*)d_in[6];
    const float* b2     = (const float*)d_in[7];
    const float* mags   = (const float*)d_in[8];
    const float* phases = (const float*)d_in[9];
    const float* oxw    = (const float*)d_in[10];
    const float* oxb    = (const float*)d_in[11];
    const float* dw     = (const float*)d_in[12];
    const float* db     = (const float*)d_in[13];
    float* out = (float*)d_out;

    float *h, *z;
    float2 *xf, *ft;
    f16 *hh, *yh, *zh, *w1h, *w1l, *w2h, *w2l, *oxh, *oxl;
    cudaGetSymbolAddress((void**)&h,   g_h);
    cudaGetSymbolAddress((void**)&z,   g_z);
    cudaGetSymbolAddress((void**)&xf,  g_xf);
    cudaGetSymbolAddress((void**)&ft,  g_filt);
    cudaGetSymbolAddress((void**)&hh,  g_h16);
    cudaGetSymbolAddress((void**)&yh,  g_y16);
    cudaGetSymbolAddress((void**)&zh,  g_z16);
    cudaGetSymbolAddress((void**)&w1h, g_w1h);
    cudaGetSymbolAddress((void**)&w1l, g_w1l);
    cudaGetSymbolAddress((void**)&w2h, g_w2h);
    cudaGetSymbolAddress((void**)&w2l, g_w2l);
    cudaGetSymbolAddress((void**)&oxh, g_oxh);
    cudaGetSymbolAddress((void**)&oxl, g_oxl);

    const int SMEM = 3 * 32768;                      // 96 KB
    static bool attr = false;
    if (!attr) {
        cudaFuncSetAttribute(gemm_mma<128, 512, 1>, cudaFuncAttributeMaxDynamicSharedMemorySize, SMEM);
        cudaFuncSetAttribute(gemm_mma<512, 128, 0>, cudaFuncAttributeMaxDynamicSharedMemorySize, SMEM);
        cudaFuncSetAttribute(gemm_mma<128, 128, 2>, cudaFuncAttributeMaxDynamicSharedMemorySize, SMEM);
        attr = true;
    }

    wsplit<<<(NLAYERS * HID * DIM + 255) / 256, 256>>>(w1, w1h, w1l, NLAYERS * HID * DIM);
    wsplit<<<(NLAYERS * DIM * HID + 255) / 256, 256>>>(w2, w2h, w2l, NLAYERS * DIM * HID);
    wsplit<<<(NLAYERS * DIM * DIM + 255) / 256, 256>>>(oxw, oxh, oxl, NLAYERS * DIM * DIM);

    enc_kernel<<<(NB * DIM * HW / 2 + 255) / 256, 256>>>(x, enc_w, enc_b, pos, h, hh);

    const size_t specL = (size_t)DIM * HH * WHF;
    for (int i = 0; i < NLAYERS; i++) {
        prep_filt<<<(int)((specL + 255) / 256), 256>>>(mags + i * specL, phases + i * specL, ft);

        gemm_mma<128, 512, 1><<<dim3(256, 4, NB), 512, SMEM>>>(
            w1h + (size_t)i * HID * DIM, w1l + (size_t)i * HID * DIM,
            hh, b1 + i * HID, nullptr, yh);
        gemm_mma<512, 128, 0><<<dim3(256, 1, NB), 512, SMEM>>>(
            w2h + (size_t)i * DIM * HID, w2l + (size_t)i * DIM * HID,
            yh, b2 + i * DIM, z, nullptr);

        fft_row_fwd<<<dim3(NB * DIM, 16), 256>>>(z, xf);
        fft_col<<<(NB * DIM * WHF) / 16, 256>>>(xf, ft);
        fft_row_inv<<<dim3(NB * DIM, 16), 256>>>(xf, zh);

        gemm_mma<128, 128, 2><<<dim3(256, 1, NB), 512, SMEM>>>(
            oxh + (size_t)i * DIM * DIM, oxl + (size_t)i * DIM * DIM,
            zh, oxb + i * DIM, h, hh);
    }

    dec_kernel<<<(NB * HW + 255) / 256, 256>>>(h, dw, db, out);
}

// round 15
// speedup vs baseline: 1.2807x; 1.1690x over previous
#include <cuda_runtime.h>
#include <cuda_fp16.h>
#include <math.h>
#include <stdint.h>

#define HH   256
#define HW   65536
#define WHF  129
#define DIM  128
#define HID  512
#define NB   4
#define NLAYERS 4
#define FSTRIDE 272   // padded row stride (float2) for the FFT shared buffer

typedef __half f16;

// ---------------- scratch (device globals) ----------------
__device__ float  g_h[(size_t)NB * DIM * HW];          // residual [b][c][p] fp32
__device__ float  g_z[(size_t)NB * DIM * HW];          // fft input fp32
__device__ __align__(16) float2 g_xf[(size_t)NB * DIM * WHF * 256];
__device__ __align__(16) float2 g_filt[(size_t)DIM * WHF * 256];
__device__ f16    g_h16[(size_t)NB * DIM * HW];        // fp16 activations
__device__ f16    g_y16[(size_t)NB * HID * HW];
__device__ f16    g_z16[(size_t)NB * DIM * HW];
__device__ f16    g_w1c[(size_t)NLAYERS * HID * DIM];
__device__ f16    g_w2c[(size_t)NLAYERS * DIM * HID];
__device__ f16    g_oxc[(size_t)NLAYERS * DIM * DIM];

// ---------------- helpers ----------------
__device__ __forceinline__ float2 cadd(float2 a, float2 b){ return make_float2(a.x+b.x, a.y+b.y); }
__device__ __forceinline__ float2 csub(float2 a, float2 b){ return make_float2(a.x-b.x, a.y-b.y); }
__device__ __forceinline__ float2 cmul(float2 a, float2 b){
    return make_float2(a.x*b.x - a.y*b.y, a.x*b.y + a.y*b.x);
}
__device__ __forceinline__ float2 cmulc(float2 a, float2 b){   // a * conj(b)
    return make_float2(a.x*b.x + a.y*b.y, a.y*b.x - a.x*b.y);
}
__device__ __forceinline__ uint32_t smem_u32(const void* p) {
    uint32_t a;
    asm("{ .reg .u64 t; cvta.to.shared.u64 t, %1; cvt.u32.u64 %0, t; }" : "=r"(a) : "l"(p));
    return a;
}
__device__ __forceinline__ uint32_t pack_f16x2(float a, float b) {
    return ((uint32_t)__half_as_ushort(__float2half_rn(b)) << 16)
         |  (uint32_t)__half_as_ushort(__float2half_rn(a));
}

// ================= mma.sync primitives =================
__device__ __forceinline__ void ldsm4(uint32_t* r, uint32_t addr) {
    asm volatile("ldmatrix.sync.aligned.m8n8.x4.shared.b16 {%0,%1,%2,%3}, [%4];"
                 : "=r"(r[0]), "=r"(r[1]), "=r"(r[2]), "=r"(r[3]) : "r"(addr));
}
__device__ __forceinline__ void ldsm4t(uint32_t* r, uint32_t addr) {
    asm volatile("ldmatrix.sync.aligned.m8n8.x4.trans.shared.b16 {%0,%1,%2,%3}, [%4];"
                 : "=r"(r[0]), "=r"(r[1]), "=r"(r[2]), "=r"(r[3]) : "r"(addr));
}
__device__ __forceinline__ void mma16816(float* c, const uint32_t* a, const uint32_t* b) {
    asm volatile(
        "mma.sync.aligned.m16n8k16.row.col.f32.f16.f16.f32 "
        "{%0,%1,%2,%3}, {%4,%5,%6,%7}, {%8,%9}, {%0,%1,%2,%3};"
        : "+f"(c[0]), "+f"(c[1]), "+f"(c[2]), "+f"(c[3])
        : "r"(a[0]), "r"(a[1]), "r"(a[2]), "r"(a[3]), "r"(b[0]), "r"(b[1]));
}
__device__ __forceinline__ void cp16(uint32_t dst, const void* src) {
    asm volatile("cp.async.cg.shared.global [%0], [%1], 16;" :: "r"(dst), "l"(src));
}

// ================= single-pass fp16 pipelined tensor-core GEMM =================
// 512 threads, tile 128m x 256n, warp grid 4x4. A = weights fp16, B = act fp16.
// Stage (24KB): [A 8K][B 16K], 3 stages = 72KB.
// EPI: 0 -> fp32 Cf; 1 -> silu -> f16 Ch; 2 -> +res(Cf) -> Cf + f16 Ch
template <int K, int M, int EPI>
__global__ void __launch_bounds__(512, 1)
gemm_mma(const f16* __restrict__ Aw, const f16* __restrict__ Bm,
         const float* __restrict__ bias,
         float* __restrict__ Cf, f16* __restrict__ Ch)
{
    constexpr int NC = K / 32;
    constexpr int STAGE = 24576;
    extern __shared__ uint8_t smem[];
    uint32_t sbase = smem_u32(smem);

    int tid  = threadIdx.x;
    int lane = tid & 31;
    int warp = tid >> 5;
    int wm = warp >> 2, wn = warp & 3;

    const f16* Ap = Aw + (size_t)blockIdx.y * 128 * K;
    const f16* Bp = Bm + (size_t)blockIdx.z * K * HW + blockIdx.x * 256;

    const f16* gp[3];
    uint32_t   off[3];
    {
        int tile = tid >> 5, line = tid & 31;
        int am  = ((tile >> 1) << 4) + (line & 15);
        int agg = ((tile & 1) << 1) + (line >> 4);
        gp[0]  = Ap + (size_t)am * K + agg * 8;
        off[0] = tile * 512 + line * 16;
        int bk  = line & 15;
        int bgn = (tile & 15) * 2 + (line >> 4);
        gp[1] = Bp + (size_t)bk * HW + bgn * 8;
        gp[2] = Bp + (size_t)(bk + 16) * HW + bgn * 8;
        off[1] = 8192 + tile * 512 + line * 16;
        off[2] = 8192 + (tile + 16) * 512 + line * 16;
    }

    auto issue = [&](int c) {
        uint32_t sst = sbase + (c % 3) * STAGE;
        cp16(sst + off[0], gp[0]);  gp[0] += 32;
        cp16(sst + off[1], gp[1]);  gp[1] += (size_t)32 * HW;
        cp16(sst + off[2], gp[2]);  gp[2] += (size_t)32 * HW;
        asm volatile("cp.async.commit_group;" ::: "memory");
    };

    float acc[2][8][4] = {};

    issue(0);
    if (NC > 1) issue(1);

    for (int c = 0; c < NC; c++) {
        if (c + 1 < NC) {
            asm volatile("cp.async.wait_group 1;" ::: "memory");
        } else {
            asm volatile("cp.async.wait_group 0;" ::: "memory");
        }
        __syncthreads();
        uint32_t st = sbase + (c % 3) * STAGE;
#pragma unroll
        for (int kb = 0; kb < 2; kb++) {
            uint32_t ah[2][4];
#pragma unroll
            for (int i = 0; i < 2; i++) {
                uint32_t ad = st + ((((wm * 2 + i) * 2) + kb) << 9) + lane * 16;
                ldsm4(ah[i], ad);
            }
#pragma unroll
            for (int r = 0; r < 4; r++) {
                uint32_t bh[4];
                uint32_t bd = st + 8192 + ((kb * 16 + wn * 4 + r) << 9) + lane * 16;
                ldsm4t(bh, bd);
#pragma unroll
                for (int i = 0; i < 2; i++)
#pragma unroll
                    for (int hh = 0; hh < 2; hh++)
                        mma16816(acc[i][r * 2 + hh], ah[i], &bh[hh * 2]);
            }
        }
        __syncthreads();
        if (c + 2 < NC) issue(c + 2);
    }

    int g = lane >> 2;
    int mb0   = blockIdx.y * 128 + wm * 32;
    int nbase = blockIdx.x * 256 + wn * 64 + (lane & 3) * 2;
    size_t batch = (size_t)blockIdx.z * M * HW;
#pragma unroll
    for (int i = 0; i < 2; i++) {
        int r0 = mb0 + i * 16 + g;
        float bi0 = bias[r0], bi1 = bias[r0 + 8];
        size_t o0 = batch + (size_t)r0 * HW + nbase;
        size_t o1 = o0 + (size_t)8 * HW;
#pragma unroll
        for (int j = 0; j < 8; j++) {
            float v0 = acc[i][j][0] + bi0, v1 = acc[i][j][1] + bi0;
            float v2 = acc[i][j][2] + bi1, v3 = acc[i][j][3] + bi1;
            if (EPI == 1) {
                v0 = v0 / (1.f + __expf(-v0)); v1 = v1 / (1.f + __expf(-v1));
                v2 = v2 / (1.f + __expf(-v2)); v3 = v3 / (1.f + __expf(-v3));
            }
            if (EPI == 2) {
                float2 r0f = *(float2*)(Cf + o0 + j * 8);
                float2 r1f = *(float2*)(Cf + o1 + j * 8);
                v0 += r0f.x; v1 += r0f.y; v2 += r1f.x; v3 += r1f.y;
            }
            if (EPI == 0 || EPI == 2) {
                *(float2*)(Cf + o0 + j * 8) = make_float2(v0, v1);
                *(float2*)(Cf + o1 + j * 8) = make_float2(v2, v3);
            }
            if (EPI == 1 || EPI == 2) {
                *(uint32_t*)(Ch + o0 + j * 8) = pack_f16x2(v0, v1);
                *(uint32_t*)(Ch + o1 + j * 8) = pack_f16x2(v2, v3);
            }
        }
    }
}

// ---------------- weight cast (fp32 -> fp16) ----------------
__global__ void wcast(const float* __restrict__ w, f16* __restrict__ wh, int n)
{
    int i = blockIdx.x * 256 + threadIdx.x;
    if (i >= n) return;
    wh[i] = __float2half_rn(w[i]);
}

// ================= four-step register FFT (256 = 16 x 16), R14 verified =================
__device__ __forceinline__ float2 tw16mul(float2 v, float c, float s, bool inv) {
    float ss = inv ? -s : s;
    return make_float2(v.x * c - v.y * ss, v.x * ss + v.y * c);
}

template <bool INV>
__device__ __forceinline__ void dft16(float2* x) {
    float2 u[16];
#pragma unroll
    for (int j1 = 0; j1 < 4; j1++) {
        float2 a = x[j1], b = x[j1 + 4], c = x[j1 + 8], d = x[j1 + 12];
        float2 t0 = cadd(a, c), t1 = csub(a, c);
        float2 t2 = cadd(b, d), t3 = csub(b, d);
        float2 r3 = INV ? make_float2(-t3.y, t3.x) : make_float2(t3.y, -t3.x);
        u[j1 * 4 + 0] = cadd(t0, t2);
        u[j1 * 4 + 1] = cadd(t1, r3);
        u[j1 * 4 + 2] = csub(t0, t2);
        u[j1 * 4 + 3] = csub(t1, r3);
    }
    u[5]  = tw16mul(u[5],  0.92387953f, -0.38268343f, INV);
    u[6]  = tw16mul(u[6],  0.70710678f, -0.70710678f, INV);
    u[7]  = tw16mul(u[7],  0.38268343f, -0.92387953f, INV);
    u[9]  = tw16mul(u[9],  0.70710678f, -0.70710678f, INV);
    u[10] = tw16mul(u[10], 0.0f,        -1.0f,        INV);
    u[11] = tw16mul(u[11], -0.70710678f,-0.70710678f, INV);
    u[13] = tw16mul(u[13], 0.38268343f, -0.92387953f, INV);
    u[14] = tw16mul(u[14], -0.70710678f,-0.70710678f, INV);
    u[15] = tw16mul(u[15], -0.92387953f, 0.38268343f, INV);
#pragma unroll
    for (int a = 0; a < 4; a++) {
        float2 p = u[a], q = u[4 + a], r = u[8 + a], s = u[12 + a];
        float2 t0 = cadd(p, r), t1 = csub(p, r);
        float2 t2 = cadd(q, s), t3 = csub(q, s);
        float2 r3 = INV ? make_float2(-t3.y, t3.x) : make_float2(t3.y, -t3.x);
        x[a + 0]  = cadd(t0, t2);
        x[a + 4]  = cadd(t1, r3);
        x[a + 8]  = csub(t0, t2);
        x[a + 12] = csub(t1, r3);
    }
}

#define TW256_INIT()                                                     \
    do { float s_, c_;                                                   \
        sincospif(-(float)threadIdx.x / 128.0f, &s_, &c_);               \
        tw[threadIdx.x] = make_float2(c_, s_); } while (0)

__global__ void fft_row_fwd(const float* __restrict__ z, float2* __restrict__ xf)
{
    __shared__ float2 sb[16 * FSTRIDE];
    __shared__ float2 tw[256];
    TW256_INIT();
    int tid = threadIdx.x;
    int r = tid >> 4, q1 = tid & 15;
    int img = blockIdx.x, y0 = blockIdx.y * 16;
    const float* src = z + (size_t)img * HW + (size_t)(y0 + r) * 256;
    float2 X[16];
#pragma unroll
    for (int n2 = 0; n2 < 16; n2++) X[n2] = make_float2(src[q1 + 16 * n2], 0.f);
    __syncthreads();
    dft16<false>(X);
#pragma unroll
    for (int k1 = 0; k1 < 16; k1++) X[k1] = cmul(X[k1], tw[q1 * k1]);
#pragma unroll
    for (int k1 = 0; k1 < 16; k1++) sb[r * FSTRIDE + k1 * 17 + q1] = X[k1];
    __syncthreads();
#pragma unroll
    for (int j = 0; j < 16; j++) X[j] = sb[r * FSTRIDE + q1 * 17 + j];
    dft16<false>(X);
    __syncthreads();
#pragma unroll
    for (int k2 = 0; k2 < 16; k2++) sb[r * FSTRIDE + q1 + 16 * k2] = X[k2];
    __syncthreads();
    float2* dst = xf + (size_t)img * (WHF * 256) + y0;
    for (int idx = tid; idx < WHF * 16; idx += 256) {
        int kx = idx >> 4, ry = idx & 15;
        dst[(size_t)kx * 256 + ry] = sb[ry * FSTRIDE + kx];
    }
}

__global__ void fft_col(float2* __restrict__ xf, const float2* __restrict__ filt)
{
    __shared__ float2 sb[16 * FSTRIDE];
    __shared__ float2 tw[256];
    TW256_INIT();
    int tid = threadIdx.x;
    int r = tid >> 4, q1 = tid & 15;
    size_t l0 = (size_t)blockIdx.x * 16;
    float2* line = xf + (l0 + r) * 256;
    float2 X[16];
#pragma unroll
    for (int n2 = 0; n2 < 16; n2++) X[n2] = line[q1 + 16 * n2];
    __syncthreads();
    dft16<false>(X);
#pragma unroll
    for (int k1 = 0; k1 < 16; k1++) X[k1] = cmul(X[k1], tw[q1 * k1]);
#pragma unroll
    for (int k1 = 0; k1 < 16; k1++) sb[r * FSTRIDE + k1 * 17 + q1] = X[k1];
    __syncthreads();
#pragma unroll
    for (int j = 0; j < 16; j++) X[j] = sb[r * FSTRIDE + q1 * 17 + j];
    dft16<false>(X);
    {
        size_t fl = ((l0 + r) % (size_t)(DIM * WHF)) * 256;
#pragma unroll
        for (int k2 = 0; k2 < 16; k2++)
            X[k2] = cmul(X[k2], filt[fl + q1 + 16 * k2]);
    }
    dft16<true>(X);
#pragma unroll
    for (int n1 = 0; n1 < 16; n1++) X[n1] = cmulc(X[n1], tw[q1 * n1]);
    __syncthreads();
#pragma unroll
    for (int n1 = 0; n1 < 16; n1++) sb[r * FSTRIDE + n1 * 17 + q1] = X[n1];
    __syncthreads();
#pragma unroll
    for (int j = 0; j < 16; j++) X[j] = sb[r * FSTRIDE + q1 * 17 + j];
    dft16<true>(X);
#pragma unroll
    for (int n2 = 0; n2 < 16; n2++) line[q1 + 16 * n2] = X[n2];
}

__global__ void fft_row_inv(const float2* __restrict__ xf, f16* __restrict__ zh)
{
    __shared__ float2 sb[16 * FSTRIDE];
    __shared__ float2 tw[256];
    TW256_INIT();
    int tid = threadIdx.x;
    int r = tid >> 4, q1 = tid & 15;
    int img = blockIdx.x, y0 = blockIdx.y * 16;
    const float2* src = xf + (size_t)img * (WHF * 256) + y0;
    for (int idx = tid; idx < WHF * 16; idx += 256) {
        int kx = idx >> 4, ry = idx & 15;
        sb[ry * FSTRIDE + kx] = src[(size_t)kx * 256 + ry];
    }
    __syncthreads();
    for (int q = tid; q < 16 * 127; q += 256) {
        int rr = q / 127;
        int k = 129 + (q % 127);
        float2 v = sb[rr * FSTRIDE + 256 - k];
        sb[rr * FSTRIDE + k] = make_float2(v.x, -v.y);
    }
    __syncthreads();
    float2 X[16];
#pragma unroll
    for (int k2 = 0; k2 < 16; k2++) X[k2] = sb[r * FSTRIDE + q1 + 16 * k2];
    __syncthreads();
    dft16<true>(X);
#pragma unroll
    for (int n1 = 0; n1 < 16; n1++) X[n1] = cmulc(X[n1], tw[q1 * n1]);
#pragma unroll
    for (int n1 = 0; n1 < 16; n1++) sb[r * FSTRIDE + n1 * 17 + q1] = X[n1];
    __syncthreads();
#pragma unroll
    for (int j = 0; j < 16; j++) X[j] = sb[r * FSTRIDE + q1 * 17 + j];
    dft16<true>(X);
    __syncthreads();
#pragma unroll
    for (int n2 = 0; n2 < 16; n2++) sb[r * FSTRIDE + q1 + 16 * n2] = X[n2];
    __syncthreads();
    size_t o = (size_t)img * HW + (size_t)y0 * 256;
    for (int idx = tid; idx < 2048; idx += 256) {
        float v0 = sb[(idx >> 7) * FSTRIDE + (idx & 127) * 2].x;
        float v1 = sb[(idx >> 7) * FSTRIDE + (idx & 127) * 2 + 1].x;
        *(uint32_t*)(zh + o + idx * 2) = pack_f16x2(v0, v1);
    }
}

// ---------------- enc / dec / filter ----------------
__global__ void enc_kernel(const float* __restrict__ x, const float* __restrict__ w,
                           const float* __restrict__ bias, const float* __restrict__ pos,
                           float* __restrict__ h, f16* __restrict__ hh)
{
    int idx = blockIdx.x * 256 + threadIdx.x;
    if (idx >= NB * DIM * HW / 2) return;
    int e = idx * 2;
    int p = e & (HW - 1);
    int o = (e >> 16) & (DIM - 1);
    int b = e >> 23;
    float x0 = x[(size_t)(b * 2 + 0) * HW + p];
    float x1 = x[(size_t)(b * 2 + 1) * HW + p];
    float x0b = x[(size_t)(b * 2 + 0) * HW + p + 1];
    float x1b = x[(size_t)(b * 2 + 1) * HW + p + 1];
    float w0 = w[o * 2], w1 = w[o * 2 + 1], bb = bias[o];
    float v0 = (w0 * x0 + w1 * x1 + bb) * 8.0f + pos[(size_t)o * HW + p];
    float v1 = (w0 * x0b + w1 * x1b + bb) * 8.0f + pos[(size_t)o * HW + p + 1];
    *(float2*)(h + e) = make_float2(v0, v1);
    *(uint32_t*)(hh + e) = pack_f16x2(v0, v1);
}

__global__ void dec_kernel(const float* __restrict__ h, const float* __restrict__ w,
                           const float* __restrict__ bias, float* __restrict__ out)
{
    int idx = blockIdx.x * 256 + threadIdx.x;
    if (idx >= NB * HW) return;
    int p = idx & (HW - 1);
    int b = idx >> 16;
    const float* hb = h + (size_t)b * DIM * HW + p;
    float a0 = 0.f, a1 = 0.f;
#pragma unroll 4
    for (int c = 0; c < DIM; c++) {
        float hv = hb[(size_t)c * HW];
        a0 += w[c] * hv;
        a1 += w[DIM + c] * hv;
    }
    out[(size_t)(b * 2 + 0) * HW + p] = (a0 + bias[0]) * 0.125f;
    out[(size_t)(b * 2 + 1) * HW + p] = (a1 + bias[1]) * 0.125f;
}

__global__ void prep_filt(const float* __restrict__ mags, const float* __restrict__ phases,
                          float2* __restrict__ filt)
{
    int idx = blockIdx.x * 256 + threadIdx.x;
    if (idx >= DIM * HH * WHF) return;
    int kx = idx % WHF;
    int ky = (idx / WHF) % HH;
    int c  = idx / (WHF * HH);
    int kyp = (ky <= 128) ? ky : (256 - ky);
    float2 o = make_float2(0.f, 0.f);
    if (kx * kx + kyp * kyp <= 16384) {
        float sig = 1.0f / (1.0f + __expf(-mags[idx]));
        float s, co;
        sincosf(phases[idx], &s, &co);
        float sc = sig * (1.0f / 65536.0f);
        o = make_float2(sc * co, sc * s);
    }
    filt[(size_t)c * (WHF * 256) + (size_t)kx * 256 + ky] = o;   // natural ky
}

// ---------------- launch ----------------
extern "C" void kernel_launch(void* const* d_in, const int* in_sizes, int n_in,
                              void* d_out, int out_size)
{
    const float* x      = (const float*)d_in[0];
    const float* enc_w  = (const float*)d_in[1];
    const float* enc_b  = (const float*)d_in[2];
    const float* pos    = (const float*)d_in[3];
    const float* w1     = (const float*)d_in[4];
    const float* b1     = (const float*)d_in[5];
    const float* w2     = (const float*)d_in[6];
    const float* b2     = (const float*)d_in[7];
    const float* mags   = (const float*)d_in[8];
    const float* phases = (const float*)d_in[9];
    const float* oxw    = (const float*)d_in[10];
    const float* oxb    = (const float*)d_in[11];
    const float* dw     = (const float*)d_in[12];
    const float* db     = (const float*)d_in[13];
    float* out = (float*)d_out;

    float *h, *z;
    float2 *xf, *ft;
    f16 *hh, *yh, *zh, *w1c, *w2c, *oxc;
    cudaGetSymbolAddress((void**)&h,   g_h);
    cudaGetSymbolAddress((void**)&z,   g_z);
    cudaGetSymbolAddress((void**)&xf,  g_xf);
    cudaGetSymbolAddress((void**)&ft,  g_filt);
    cudaGetSymbolAddress((void**)&hh,  g_h16);
    cudaGetSymbolAddress((void**)&yh,  g_y16);
    cudaGetSymbolAddress((void**)&zh,  g_z16);
    cudaGetSymbolAddress((void**)&w1c, g_w1c);
    cudaGetSymbolAddress((void**)&w2c, g_w2c);
    cudaGetSymbolAddress((void**)&oxc, g_oxc);

    const int SMEM = 3 * 24576;                      // 72 KB
    static bool attr = false;
    if (!attr) {
        cudaFuncSetAttribute(gemm_mma<128, 512, 1>, cudaFuncAttributeMaxDynamicSharedMemorySize, SMEM);
        cudaFuncSetAttribute(gemm_mma<512, 128, 0>, cudaFuncAttributeMaxDynamicSharedMemorySize, SMEM);
        cudaFuncSetAttribute(gemm_mma<128, 128, 2>, cudaFuncAttributeMaxDynamicSharedMemorySize, SMEM);
        attr = true;
    }

    wcast<<<(NLAYERS * HID * DIM + 255) / 256, 256>>>(w1, w1c, NLAYERS * HID * DIM);
    wcast<<<(NLAYERS * DIM * HID + 255) / 256, 256>>>(w2, w2c, NLAYERS * DIM * HID);
    wcast<<<(NLAYERS * DIM * DIM + 255) / 256, 256>>>(oxw, oxc, NLAYERS * DIM * DIM);

    enc_kernel<<<(NB * DIM * HW / 2 + 255) / 256, 256>>>(x, enc_w, enc_b, pos, h, hh);

    const size_t specL = (size_t)DIM * HH * WHF;
    for (int i = 0; i < NLAYERS; i++) {
        prep_filt<<<(int)((specL + 255) / 256), 256>>>(mags + i * specL, phases + i * specL, ft);

        gemm_mma<128, 512, 1><<<dim3(256, 4, NB), 512, SMEM>>>(
            w1c + (size_t)i * HID * DIM, hh, b1 + i * HID, nullptr, yh);
        gemm_mma<512, 128, 0><<<dim3(256, 1, NB), 512, SMEM>>>(
            w2c + (size_t)i * DIM * HID, yh, b2 + i * DIM, z, nullptr);

        fft_row_fwd<<<dim3(NB * DIM, 16), 256>>>(z, xf);
        fft_col<<<(NB * DIM * WHF) / 16, 256>>>(xf, ft);
        fft_row_inv<<<dim3(NB * DIM, 16), 256>>>(xf, zh);

        gemm_mma<128, 128, 2><<<dim3(256, 1, NB), 512, SMEM>>>(
            oxc + (size_t)i * DIM * DIM, zh, oxb + i * DIM, h, hh);
    }

    dec_kernel<<<(NB * HW + 255) / 256, 256>>>(h, dw, db, out);
}